// round 14
// baseline (speedup 1.0000x reference)
#include <cuda_runtime.h>
#include <cstdint>

// ============================================================================
// CgpHmmCell: HMM forward scan. B=128, T=8192, S=512, M=64.
//
// Linear-domain rescaled recurrence (exactly the reference math):
//   F_0[b][s] = (s==0) ? E_0[b][0]+eps : 0 ;  C_0 = 0
//   step t:    M = max_s F_{t-1}[b][s] ;  C += log(M)  (Kahan)
//              y[b][j]   = sum_s F_{t-1}[b][s] * A[s][j]
//              F_t[b][j] = (E_t[b][j]+eps) * (y * (1/M) + eps)
//   alpha_T = log(F_T) + C ;  loglik = log(sum F_T/M_T + S*eps) + log(M_T) + C
//
// 16 teams x 8-CTA clusters, 512 threads/CTA. Exchange via st.async with
// PER-SOURCE parity mbarriers: warp w consumes only source (w>>1)'s s-slice,
// so it waits only that source's 2112B — exchange tail overlaps with MAC.
// (Round-12 fix: phase parity flips ONLY when a wait actually occurred.)
// ============================================================================

#define T_LEN 8192
#define EPS   1e-16f

typedef unsigned long long ull;

// word-offset smem map
#define FSTR      514                  // F batch stride (bank padding)
#define FBUFW     4112                 // 8 * FSTR
#define OFF_FB    32768                // fb[2][8][FSTR]
#define OFF_PART  40992                // part[32][512]
#define OFF_MAXB  57376                // maxb[2][8 b][16 src]
#define OFF_CV    57632                // cvs[8]
#define OFF_MBAR  57640                // 16 x u64 mbarrier [parity][src]
#define SMEM_WORDS 57672
#define SMEM_BYTES (SMEM_WORDS * 4)    // 230688 <= 232448

// per-source incoming per step: 8b x 64j x 4B + 16 x 4B = 2112
#define TXS_BYTES 2112

__device__ unsigned char g_sym[128 * T_LEN];

// ---------------------------------------------------------------------------
__global__ void sym_kernel(const float* __restrict__ x) {
    int gw   = (blockIdx.x * blockDim.x + threadIdx.x) >> 5;
    int lane = threadIdx.x & 31;
    if (gw >= 128 * T_LEN) return;
    const float* p = x + (size_t)gw * 64;
    unsigned m1 = __ballot_sync(0xffffffffu, p[lane] > 0.5f);
    unsigned m2 = __ballot_sync(0xffffffffu, p[lane + 32] > 0.5f);
    if (lane == 0)
        g_sym[gw] = (unsigned char)(m1 ? (__ffs(m1) - 1) : (31 + __ffs(m2)));
}

// ---------------------------------------------------------------------------
__device__ __forceinline__ uint32_t smem_u32(const void* p) {
    uint32_t a;
    asm("{ .reg .u64 t; cvta.to.shared.u64 t, %1; cvt.u32.u64 %0, t; }"
        : "=r"(a) : "l"(p));
    return a;
}
__device__ __forceinline__ uint32_t mapa_u32(uint32_t a, uint32_t r) {
    uint32_t o;
    asm("mapa.shared::cluster.u32 %0, %1, %2;" : "=r"(o) : "r"(a), "r"(r));
    return o;
}
__device__ __forceinline__ void mb_init(uint32_t a, uint32_t cnt) {
    asm volatile("mbarrier.init.shared.b64 [%0], %1;" :: "r"(a), "r"(cnt) : "memory");
}
__device__ __forceinline__ void mb_expect(uint32_t a, uint32_t bytes) {
    asm volatile("mbarrier.arrive.expect_tx.shared.b64 _, [%0], %1;"
                 :: "r"(a), "r"(bytes) : "memory");
}
__device__ __forceinline__ void mb_wait(uint32_t a, uint32_t parity) {
    asm volatile(
        "{\n\t.reg .pred P;\n\t"
        "WL_%=:\n\t"
        "mbarrier.try_wait.parity.acquire.cta.shared::cta.b64 P, [%0], %1, 0x989680;\n\t"
        "@P bra.uni WD_%=;\n\t"
        "bra.uni WL_%=;\n\t"
        "WD_%=:\n\t}"
        :: "r"(a), "r"(parity) : "memory");
}
__device__ __forceinline__ void sta_b64(uint32_t dst, ull v, uint32_t mbar) {
    asm volatile(
        "st.async.shared::cluster.mbarrier::complete_tx::bytes.b64 [%0], %1, [%2];"
        :: "r"(dst), "l"(v), "r"(mbar) : "memory");
}
__device__ __forceinline__ void sta_b32(uint32_t dst, uint32_t v, uint32_t mbar) {
    asm volatile(
        "st.async.shared::cluster.mbarrier::complete_tx::bytes.b32 [%0], %1, [%2];"
        :: "r"(dst), "r"(v), "r"(mbar) : "memory");
}
__device__ __forceinline__ void cluster_arrive() {
    asm volatile("barrier.cluster.arrive.aligned;" ::: "memory");
}
__device__ __forceinline__ void cluster_wait() {
    asm volatile("barrier.cluster.wait.aligned;" ::: "memory");
}
#define FMA2(d, a, b) \
    asm("fma.rn.f32x2 %0, %1, %2, %0;" : "+l"(d) : "l"(a), "l"(b))
#define DUP2(d, f) \
    asm("mov.b64 %0, {%1, %1};" : "=l"(d) : "f"(f))

// ---------------------------------------------------------------------------
__global__ void __launch_bounds__(512, 1) __cluster_dims__(8, 1, 1)
hmm_kernel(const float* __restrict__ A, const float* __restrict__ Bm,
           float* __restrict__ out, int out_size) {
    extern __shared__ float sm[];
    float* fb   = sm + OFF_FB;
    float* part = sm + OFF_PART;
    float* maxb = sm + OFF_MAXB;
    float* cvs  = sm + OFF_CV;

    int tid = threadIdx.x;
    uint32_t rank;
    asm("mov.u32 %0, %%cluster_ctarank;" : "=r"(rank));
    int team = blockIdx.x >> 3;
    int wid = tid >> 5, lane = tid & 31;

    uint32_t base = smem_u32(sm);
    uint32_t mb_local = base + OFF_MBAR * 4;

    // ---- load A slice row-major: As[s][64] ----
    for (int i = tid; i < 512 * 64; i += 512) {
        int s = i >> 6, j = i & 63;
        sm[i] = A[s * 512 + (rank << 6) + j];
    }
    // ---- init fb (both parities), maxb, 16 mbarriers ----
    for (int i = tid; i < 2 * FBUFW; i += 512) fb[i] = 0.0f;
    for (int i = tid; i < 256; i += 512) maxb[i] = 0.0f;
    if (tid < 16) mb_init(mb_local + tid * 8, 1);
    __syncthreads();
    if (tid < 8) {
        int bglob = team * 8 + tid;
        float e0 = Bm[(int)g_sym[(size_t)bglob * T_LEN] * 512] + EPS;
        fb[tid * FSTR] = e0;               // F0[b][0], parity 0
        maxb[tid * 16] = e0;               // parity0, b=tid, src0
    }
    __syncthreads();
    cluster_arrive(); cluster_wait();      // one-time: peers seeded + mbar init

    // peer smem bases, rotated push order (self first, then rank+1, ...)
    uint32_t pb[8];
    #pragma unroll
    for (int c = 0; c < 8; ++c) pb[c] = mapa_u32(base, (rank + c) & 7);

    // finalize identity: one (b, j) per thread
    int ob = tid >> 6, oj = tid & 63;
    int bglob = team * 8 + ob;
    const unsigned char* symrow = g_sym + (size_t)bglob * T_LEN;
    const float* Bcol = Bm + (rank << 6) + oj;
    uint32_t fpush_rel = (uint32_t)(OFF_FB + ob * FSTR + (rank << 6) + oj) << 2;
    uint32_t mpush_rel = (uint32_t)(OFF_MAXB + ob * 16 + (rank << 1) + (wid & 1)) << 2;

    // MAC identity: jg j-group, bg batch-half, kg s-chunk; warp's source slice
    int jg = tid & 7, bg = (tid >> 3) & 1, kg = tid >> 4;
    uint32_t wsrc = (uint32_t)(wid >> 1);          // source CTA for this warp's s

    float Cv = 0.0f, Ck = 0.0f;            // Kahan C (oj==0 threads)
    int ph0 = 0, ph1 = 0;                  // phase parities

    for (int t = 1; t < T_LEN; ++t) {
        int p = t & 1, rp = p ^ 1;

        // arm this step's incoming per-source barriers
        if (tid < 8) mb_expect(mb_local + (uint32_t)((p << 3) + tid) * 8, TXS_BYTES);

        // E prefetch (independent of exchange)
        float e = Bcol[(int)symrow[t] * 512];

        // wait ONLY this warp's source slice (t=1 seeded locally);
        // flip parity ONLY when a wait occurred (round-12 deadlock fix)
        if (t > 1) {
            mb_wait(mb_local + (uint32_t)((rp << 3) + wsrc) * 8, rp ? ph1 : ph0);
            if (rp) ph1 ^= 1; else ph0 ^= 1;
        }

        // ---- MAC: acc[4 batches][4 f32x2] over this thread's 16 s ----
        const float* Frd  = fb + (rp ? FBUFW : 0) + bg * (4 * FSTR) + (kg << 4);
        const float* Arow = sm + (kg << 10) + (jg << 2);
        ull acc0[4], acc1[4], acc2[4], acc3[4];
        #pragma unroll
        for (int bi = 0; bi < 4; ++bi) { acc0[bi]=0; acc1[bi]=0; acc2[bi]=0; acc3[bi]=0; }

        #pragma unroll
        for (int sp = 0; sp < 8; ++sp) {
            const float* ar = Arow + (sp << 7);           // rows 2sp, 2sp+1
            ulonglong2 A0  = *(const ulonglong2*)(ar);
            ulonglong2 A0h = *(const ulonglong2*)(ar + 32);
            ulonglong2 A1  = *(const ulonglong2*)(ar + 64);
            ulonglong2 A1h = *(const ulonglong2*)(ar + 96);
            #pragma unroll
            for (int bi = 0; bi < 4; ++bi) {
                float2 f2 = *(const float2*)(Frd + bi * FSTR + (sp << 1));
                ull flo, fhi;
                DUP2(flo, f2.x);
                DUP2(fhi, f2.y);
                FMA2(acc0[bi], A0.x,  flo);
                FMA2(acc1[bi], A0.y,  flo);
                FMA2(acc2[bi], A0h.x, flo);
                FMA2(acc3[bi], A0h.y, flo);
                FMA2(acc0[bi], A1.x,  fhi);
                FMA2(acc1[bi], A1.y,  fhi);
                FMA2(acc2[bi], A1h.x, fhi);
                FMA2(acc3[bi], A1h.y, fhi);
            }
        }

        // ---- stage partials: part[kg][(bg*4+bi)*64 + jcol] ----
        float* prow = part + (kg << 9) + (bg << 8) + (jg << 2);
        #pragma unroll
        for (int bi = 0; bi < 4; ++bi) {
            *(ulonglong2*)(prow + bi * 64)      = make_ulonglong2(acc0[bi], acc1[bi]);
            *(ulonglong2*)(prow + bi * 64 + 32) = make_ulonglong2(acc2[bi], acc3[bi]);
        }
        __syncthreads();

        // ---- reduce 32 partials ----
        float s0 = 0, s1 = 0, s2 = 0, s3 = 0;
        const float* pc = part + tid;
        #pragma unroll
        for (int k = 0; k < 32; k += 4) {
            s0 += pc[k * 512];        s1 += pc[(k + 1) * 512];
            s2 += pc[(k + 2) * 512];  s3 += pc[(k + 3) * 512];
        }
        float y = (s0 + s1) + (s2 + s3);

        // ---- per-thread invM (broadcast reads of maxb[rp][ob][0..15]) ----
        const float* mr = maxb + (rp << 7) + (ob << 4);
        float M = mr[0];
        #pragma unroll
        for (int c = 1; c < 16; ++c) M = fmaxf(M, mr[c]);
        float inv = 1.0f / M;

        // ---- Kahan C (oj==0 threads; logf off critical path) ----
        if (oj == 0) {
            float yv = logf(M) - Ck;
            float tt = Cv + yv;
            Ck = (tt - Cv) - yv;
            Cv = tt;
        }

        float fnew = (e + EPS) * (y * inv + EPS);

        // ---- push F pairs to all 8 CTAs (self first, rotated) ----
        float fhi_v = __shfl_down_sync(0xffffffffu, fnew, 1);
        uint32_t mb_off = (uint32_t)(OFF_MBAR << 2) + (uint32_t)((p << 3) + rank) * 8;
        if ((oj & 1) == 0) {
            ull pr;
            asm("mov.b64 %0, {%1, %2};" : "=l"(pr) : "f"(fnew), "f"(fhi_v));
            uint32_t rel = fpush_rel + ((uint32_t)(p * FBUFW) << 2);
            #pragma unroll
            for (int c = 0; c < 8; ++c)
                sta_b64(pb[c] + rel, pr, pb[c] + mb_off);
        }

        // ---- warp half-batch max -> push to all maxbufs ----
        float wm = fnew;
        #pragma unroll
        for (int o2 = 16; o2; o2 >>= 1)
            wm = fmaxf(wm, __shfl_xor_sync(0xffffffffu, wm, o2));
        if (lane == 0) {
            uint32_t rel = mpush_rel + ((uint32_t)(p << 7) << 2);
            uint32_t wv = __float_as_uint(wm);
            #pragma unroll
            for (int c = 0; c < 8; ++c)
                sta_b32(pb[c] + rel, wv, pb[c] + mb_off);
        }
        __syncthreads();   // protect 'part' against next step's staging
    }

    // ---- epilogue: wait ALL parity-1 source barriers, then outputs ----
    #pragma unroll
    for (int c = 0; c < 8; ++c)
        mb_wait(mb_local + (uint32_t)(8 + c) * 8, ph1);
    if (oj == 0) cvs[ob] = Cv;
    __syncthreads();

    {
        float F = fb[FBUFW + ob * FSTR + (rank << 6) + oj];   // parity 1
        float alpha = logf(F) + cvs[ob];
        if (out_size >= 65536)
            out[(size_t)bglob * 512 + (rank << 6) + oj] = alpha;
    }

    if (rank == 0 && wid < 8) {
        int b = wid;
        const float* fr = fb + FBUFW + b * FSTR;
        float sum = 0.0f;
        for (int s = lane; s < 512; s += 32) sum += fr[s];
        #pragma unroll
        for (int o2 = 16; o2; o2 >>= 1)
            sum += __shfl_xor_sync(0xffffffffu, sum, o2);
        if (lane == 0) {
            const float* mr = maxb + 128 + (b << 4);          // parity 1
            float M = mr[0];
            #pragma unroll
            for (int c = 1; c < 16; ++c) M = fmaxf(M, mr[c]);
            float ll = logf(sum / M + 512.0f * EPS) + logf(M) + cvs[b];
            if (out_size >= 65664)      out[65536 + team * 8 + b] = ll;
            else if (out_size == 128)   out[team * 8 + b] = ll;
        }
    }
}

// ---------------------------------------------------------------------------
extern "C" void kernel_launch(void* const* d_in, const int* in_sizes, int n_in,
                              void* d_out, int out_size) {
    const float* x = nullptr; const float* A = nullptr; const float* Bm = nullptr;
    for (int i = 0; i < n_in; ++i) {
        if (in_sizes[i] == 128 * T_LEN * 64)      x  = (const float*)d_in[i];
        else if (in_sizes[i] == 512 * 512)        A  = (const float*)d_in[i];
        else if (in_sizes[i] == 64 * 512)         Bm = (const float*)d_in[i];
    }
    if (!x)  x  = (const float*)d_in[0];
    if (!A)  A  = (const float*)d_in[1];
    if (!Bm) Bm = (const float*)d_in[2];

    cudaFuncSetAttribute(hmm_kernel,
                         cudaFuncAttributeMaxDynamicSharedMemorySize,
                         SMEM_BYTES);

    sym_kernel<<<(128 * T_LEN) / 8, 256>>>(x);
    hmm_kernel<<<128, 512, SMEM_BYTES>>>(A, Bm, (float*)d_out, out_size);
}

// round 16
// speedup vs baseline: 1.2207x; 1.2207x over previous
#include <cuda_runtime.h>
#include <cstdint>

// ============================================================================
// CgpHmmCell: HMM forward scan. B=128, T=8192, S=512, M=64.
//
// Linear-domain rescaled recurrence (exactly the reference math):
//   F_0[b][s] = (s==0) ? E_0[b][0]+eps : 0 ;  C_0 = 0
//   step t:    M = max_s F_{t-1}[b][s] ;  C += log(M)  (Kahan)
//              y[b][j]   = sum_s F_{t-1}[b][s] * A[s][j]
//              F_t[b][j] = (E_t[b][j]+eps) * (y * (1/M) + eps)
//   alpha_T = log(F_T) + C ;  loglik = log(sum F_T/M_T + S*eps) + log(M_T) + C
//
// 16 teams x 8-CTA clusters, 512 threads/CTA. F replicated via cp.async.bulk
// SMEM->SMEM cluster copies (7 descriptors/step/CTA) completing on per-source
// parity mbarriers — replaces ~2100 scalar st.async per step (LSU drain).
// Finalize writes directly into the CTA's own contiguous slot (no self copy).
// ============================================================================

#define T_LEN 8192
#define EPS   1e-16f

typedef unsigned long long ull;

// word-offset smem map
#define SLOTW     544                  // per-source slot: 8b*66 + 16 max
#define BSTR      66                   // batch stride inside slot (bank spread)
#define PARW      4352                 // 8 * SLOTW (one parity)
#define OFF_FSLOT 32768                // fslot[2][8][SLOTW]
#define OFF_PART  41472                // part[32][512]
#define OFF_CV    57856                // cvs[8]
#define OFF_MBAR  57864                // 16 x u64 mbarrier [parity][src]
#define SMEM_WORDS 57896
#define SMEM_BYTES (SMEM_WORDS * 4)    // 231584 <= 232448

#define TXS_BYTES 2176                 // SLOTW * 4

__device__ unsigned char g_sym[128 * T_LEN];

// ---------------------------------------------------------------------------
__global__ void sym_kernel(const float* __restrict__ x) {
    int gw   = (blockIdx.x * blockDim.x + threadIdx.x) >> 5;
    int lane = threadIdx.x & 31;
    if (gw >= 128 * T_LEN) return;
    const float* p = x + (size_t)gw * 64;
    unsigned m1 = __ballot_sync(0xffffffffu, p[lane] > 0.5f);
    unsigned m2 = __ballot_sync(0xffffffffu, p[lane + 32] > 0.5f);
    if (lane == 0)
        g_sym[gw] = (unsigned char)(m1 ? (__ffs(m1) - 1) : (31 + __ffs(m2)));
}

// ---------------------------------------------------------------------------
__device__ __forceinline__ uint32_t smem_u32(const void* p) {
    uint32_t a;
    asm("{ .reg .u64 t; cvta.to.shared.u64 t, %1; cvt.u32.u64 %0, t; }"
        : "=r"(a) : "l"(p));
    return a;
}
__device__ __forceinline__ uint32_t mapa_u32(uint32_t a, uint32_t r) {
    uint32_t o;
    asm("mapa.shared::cluster.u32 %0, %1, %2;" : "=r"(o) : "r"(a), "r"(r));
    return o;
}
__device__ __forceinline__ void mb_init(uint32_t a, uint32_t cnt) {
    asm volatile("mbarrier.init.shared.b64 [%0], %1;" :: "r"(a), "r"(cnt) : "memory");
}
__device__ __forceinline__ void mb_expect(uint32_t a, uint32_t bytes) {
    asm volatile("mbarrier.arrive.expect_tx.shared.b64 _, [%0], %1;"
                 :: "r"(a), "r"(bytes) : "memory");
}
__device__ __forceinline__ void mb_wait(uint32_t a, uint32_t parity) {
    asm volatile(
        "{\n\t.reg .pred P;\n\t"
        "WL_%=:\n\t"
        "mbarrier.try_wait.parity.acquire.cta.shared::cta.b64 P, [%0], %1, 0x989680;\n\t"
        "@P bra.uni WD_%=;\n\t"
        "bra.uni WL_%=;\n\t"
        "WD_%=:\n\t}"
        :: "r"(a), "r"(parity) : "memory");
}
// SMEM(cta) -> SMEM(cluster peer) bulk copy, completes on peer's mbarrier
__device__ __forceinline__ void bulk_smem_to_peer(uint32_t dst, uint32_t src,
                                                  uint32_t bytes, uint32_t mbar) {
    asm volatile(
        "cp.async.bulk.shared::cluster.shared::cta.mbarrier::complete_tx::bytes "
        "[%0], [%1], %2, [%3];"
        :: "r"(dst), "r"(src), "r"(bytes), "r"(mbar) : "memory");
}
__device__ __forceinline__ void fence_proxy_async_cta() {
    asm volatile("fence.proxy.async.shared::cta;" ::: "memory");
}
__device__ __forceinline__ void cluster_arrive() {
    asm volatile("barrier.cluster.arrive.aligned;" ::: "memory");
}
__device__ __forceinline__ void cluster_wait() {
    asm volatile("barrier.cluster.wait.aligned;" ::: "memory");
}
#define FMA2(d, a, b) \
    asm("fma.rn.f32x2 %0, %1, %2, %0;" : "+l"(d) : "l"(a), "l"(b))
#define DUP2(d, f) \
    asm("mov.b64 %0, {%1, %1};" : "=l"(d) : "f"(f))

// ---------------------------------------------------------------------------
__global__ void __launch_bounds__(512, 1) __cluster_dims__(8, 1, 1)
hmm_kernel(const float* __restrict__ A, const float* __restrict__ Bm,
           float* __restrict__ out, int out_size) {
    extern __shared__ float sm[];
    float* fsl  = sm + OFF_FSLOT;
    float* part = sm + OFF_PART;
    float* cvs  = sm + OFF_CV;

    int tid = threadIdx.x;
    uint32_t rank;
    asm("mov.u32 %0, %%cluster_ctarank;" : "=r"(rank));
    int team = blockIdx.x >> 3;
    int wid = tid >> 5, lane = tid & 31;

    uint32_t base = smem_u32(sm);

    // ---- load A slice row-major: As[s][64] ----
    for (int i = tid; i < 512 * 64; i += 512) {
        int s = i >> 6, j = i & 63;
        sm[i] = A[s * 512 + (rank << 6) + j];
    }
    // ---- init fslot (both parities), mbarriers ----
    for (int i = tid; i < 2 * PARW; i += 512) fsl[i] = 0.0f;
    if (tid < 16) mb_init(base + (OFF_MBAR << 2) + tid * 8, 1);
    __syncthreads();
    if (tid < 8) {
        int bglob = team * 8 + tid;
        float e0 = Bm[(int)g_sym[(size_t)bglob * T_LEN] * 512] + EPS;
        fsl[tid * BSTR] = e0;              // F0[b][s=0] -> slot src0, parity 0
        fsl[528 + (tid << 1)] = e0;        // max slot src0, half 0
    }
    __syncthreads();
    cluster_arrive(); cluster_wait();      // one-time: peers seeded + mbar init

    // peer smem bases, rotated (pb[0] == self)
    uint32_t pb[8];
    #pragma unroll
    for (int c = 0; c < 8; ++c) pb[c] = mapa_u32(base, (rank + c) & 7);

    // finalize identity: one (b, j) per thread
    int ob = tid >> 6, oj = tid & 63;
    int bglob = team * 8 + ob;
    const unsigned char* symrow = g_sym + (size_t)bglob * T_LEN;
    const float* Bcol = Bm + (rank << 6) + oj;
    // my own slot, word offset of (parity 0): OFF_FSLOT + rank*SLOTW
    uint32_t myslot_w = (uint32_t)(OFF_FSLOT + rank * SLOTW);

    // MAC identity: jg j-group, bg batch-half, kg s-chunk; warp's source slice
    int jg = tid & 7, bg = (tid >> 3) & 1, kg = tid >> 4;
    uint32_t wsrc = (uint32_t)(wid >> 1);          // source CTA for this warp's s

    float Cv = 0.0f, Ck = 0.0f;            // Kahan C (oj==0 threads)
    int ph0 = 0, ph1 = 0;                  // phase parities

    for (int t = 1; t < T_LEN; ++t) {
        int p = t & 1, rp = p ^ 1;

        // arm this step's incoming per-source barriers (no self tx)
        if (tid < 8 && (uint32_t)tid != rank)
            mb_expect(base + (OFF_MBAR << 2) + (uint32_t)((p << 3) + tid) * 8,
                      TXS_BYTES);

        // E prefetch
        float e = Bcol[(int)symrow[t] * 512];

        // wait ONLY this warp's source slice (self slice is local);
        // parity flips every step t>1 for ALL warps (keeps schedule uniform)
        if (t > 1) {
            if (wsrc != rank)
                mb_wait(base + (OFF_MBAR << 2) + (uint32_t)((rp << 3) + wsrc) * 8,
                        rp ? ph1 : ph0);
            if (rp) ph1 ^= 1; else ph0 ^= 1;
        }

        // ---- MAC: acc[4 batches][4 f32x2] over this thread's 16 s ----
        const float* Frd = fsl + (rp ? PARW : 0) + (kg >> 2) * SLOTW
                         + (bg * 4) * BSTR + ((kg & 3) << 4);
        const float* Arow = sm + (kg << 10) + (jg << 2);
        ull acc0[4], acc1[4], acc2[4], acc3[4];
        #pragma unroll
        for (int bi = 0; bi < 4; ++bi) { acc0[bi]=0; acc1[bi]=0; acc2[bi]=0; acc3[bi]=0; }

        #pragma unroll
        for (int sp = 0; sp < 8; ++sp) {
            const float* ar = Arow + (sp << 7);           // rows 2sp, 2sp+1
            ulonglong2 A0  = *(const ulonglong2*)(ar);
            ulonglong2 A0h = *(const ulonglong2*)(ar + 32);
            ulonglong2 A1  = *(const ulonglong2*)(ar + 64);
            ulonglong2 A1h = *(const ulonglong2*)(ar + 96);
            #pragma unroll
            for (int bi = 0; bi < 4; ++bi) {
                float2 f2 = *(const float2*)(Frd + bi * BSTR + (sp << 1));
                ull flo, fhi;
                DUP2(flo, f2.x);
                DUP2(fhi, f2.y);
                FMA2(acc0[bi], A0.x,  flo);
                FMA2(acc1[bi], A0.y,  flo);
                FMA2(acc2[bi], A0h.x, flo);
                FMA2(acc3[bi], A0h.y, flo);
                FMA2(acc0[bi], A1.x,  fhi);
                FMA2(acc1[bi], A1.y,  fhi);
                FMA2(acc2[bi], A1h.x, fhi);
                FMA2(acc3[bi], A1h.y, fhi);
            }
        }

        // ---- stage partials: part[kg][(bg*4+bi)*64 + jcol] ----
        float* prow = part + (kg << 9) + (bg << 8) + (jg << 2);
        #pragma unroll
        for (int bi = 0; bi < 4; ++bi) {
            *(ulonglong2*)(prow + bi * 64)      = make_ulonglong2(acc0[bi], acc1[bi]);
            *(ulonglong2*)(prow + bi * 64 + 32) = make_ulonglong2(acc2[bi], acc3[bi]);
        }
        __syncthreads();

        // ---- reduce 32 partials ----
        float s0 = 0, s1 = 0, s2 = 0, s3 = 0;
        const float* pc = part + tid;
        #pragma unroll
        for (int k = 0; k < 32; k += 4) {
            s0 += pc[k * 512];        s1 += pc[(k + 1) * 512];
            s2 += pc[(k + 2) * 512];  s3 += pc[(k + 3) * 512];
        }
        float y = (s0 + s1) + (s2 + s3);

        // ---- per-thread invM: max over 8 slots x 2 halves (post-bar safe) ----
        const float* fr = fsl + (rp ? PARW : 0) + 528 + (ob << 1);
        float M = fr[0];
        M = fmaxf(M, fr[1]);
        #pragma unroll
        for (int c = 1; c < 8; ++c) {
            M = fmaxf(M, fr[c * SLOTW]);
            M = fmaxf(M, fr[c * SLOTW + 1]);
        }
        float inv = 1.0f / M;

        // ---- Kahan C (oj==0 threads; logf off critical path) ----
        if (oj == 0) {
            float yv = logf(M) - Ck;
            float tt = Cv + yv;
            Ck = (tt - Cv) - yv;
            Cv = tt;
        }

        float fnew = (e + EPS) * (y * inv + EPS);

        // ---- write into my own slot (parity p): F + warp max ----
        float* ms = sm + myslot_w + (p ? PARW : 0);
        ms[ob * BSTR + oj] = fnew;
        float wm = fnew;
        #pragma unroll
        for (int o2 = 16; o2; o2 >>= 1)
            wm = fmaxf(wm, __shfl_xor_sync(0xffffffffu, wm, o2));
        if (lane == 0) ms[528 + (ob << 1) + (wid & 1)] = wm;
        __syncthreads();   // slot complete + protect 'part'

        // ---- one thread ships the slot to all 7 peers (async DMA) ----
        if (tid == 0) {
            fence_proxy_async_cta();
            uint32_t soff = (myslot_w + (uint32_t)(p ? PARW : 0)) << 2;
            uint32_t moff = (uint32_t)(OFF_MBAR << 2) + (uint32_t)((p << 3) + rank) * 8;
            #pragma unroll
            for (int c = 1; c < 8; ++c)
                bulk_smem_to_peer(pb[c] + soff, base + soff, TXS_BYTES,
                                  pb[c] + moff);
        }
    }

    // ---- epilogue: wait final (parity 1) slices from all remote sources ----
    #pragma unroll
    for (int c = 0; c < 8; ++c)
        if ((uint32_t)c != rank)
            mb_wait(base + (OFF_MBAR << 2) + (uint32_t)(8 + c) * 8, ph1);
    if (oj == 0) cvs[ob] = Cv;
    __syncthreads();

    {
        float F = fsl[PARW + rank * SLOTW + ob * BSTR + oj];   // own slot, parity 1
        float alpha = logf(F) + cvs[ob];
        if (out_size >= 65536)
            out[(size_t)bglob * 512 + (rank << 6) + oj] = alpha;
    }

    if (rank == 0 && wid < 8) {
        int b = wid;
        const float* f1 = fsl + PARW;
        float sum = 0.0f;
        for (int s = lane; s < 512; s += 32)
            sum += f1[(s >> 6) * SLOTW + b * BSTR + (s & 63)];
        #pragma unroll
        for (int o2 = 16; o2; o2 >>= 1)
            sum += __shfl_xor_sync(0xffffffffu, sum, o2);
        if (lane == 0) {
            float M = f1[528 + (b << 1)];
            M = fmaxf(M, f1[528 + (b << 1) + 1]);
            #pragma unroll
            for (int c = 1; c < 8; ++c) {
                M = fmaxf(M, f1[c * SLOTW + 528 + (b << 1)]);
                M = fmaxf(M, f1[c * SLOTW + 528 + (b << 1) + 1]);
            }
            float ll = logf(sum / M + 512.0f * EPS) + logf(M) + cvs[b];
            if (out_size >= 65664)      out[65536 + team * 8 + b] = ll;
            else if (out_size == 128)   out[team * 8 + b] = ll;
        }
    }
}

// ---------------------------------------------------------------------------
extern "C" void kernel_launch(void* const* d_in, const int* in_sizes, int n_in,
                              void* d_out, int out_size) {
    const float* x = nullptr; const float* A = nullptr; const float* Bm = nullptr;
    for (int i = 0; i < n_in; ++i) {
        if (in_sizes[i] == 128 * T_LEN * 64)      x  = (const float*)d_in[i];
        else if (in_sizes[i] == 512 * 512)        A  = (const float*)d_in[i];
        else if (in_sizes[i] == 64 * 512)         Bm = (const float*)d_in[i];
    }
    if (!x)  x  = (const float*)d_in[0];
    if (!A)  A  = (const float*)d_in[1];
    if (!Bm) Bm = (const float*)d_in[2];

    cudaFuncSetAttribute(hmm_kernel,
                         cudaFuncAttributeMaxDynamicSharedMemorySize,
                         SMEM_BYTES);

    sym_kernel<<<(128 * T_LEN) / 8, 256>>>(x);
    hmm_kernel<<<128, 512, SMEM_BYTES>>>(A, Bm, (float*)d_out, out_size);
}